// round 1
// baseline (speedup 1.0000x reference)
#include <cuda_runtime.h>
#include <cuda_bf16.h>

// Problem constants (HGAT_9543417332149): B=8, N=2048, E=64, F=NH=64, FC=2*NH=128
#define BB 8
#define NN 2048
#define EE 64
#define FF 64
#define FC 128

// -------- device scratch (no allocations allowed) --------
__device__ float g_h[BB * NN * FF];     // h = x @ W
__device__ float g_xw[BB * NN * FF];    // x @ W_ind
__device__ float g_s[BB * NN];          // leaky_relu(h @ a_node)
__device__ float g_hn[BB * NN];         // h @ a_gn
__device__ float g_agg[BB * EE * FF];   // hyperedge embedding (raw, pre-elu)
__device__ float g_ge[BB * EE];         // agg @ a_ge
__device__ float g_se[BB * EE];         // edge scores from elu(agg)
__device__ float g_ind[BB * NN * FF];   // industry features
__device__ int   g_emem[EE * NN];       // per-edge member node lists
__device__ int   g_ecnt[EE];            // per-edge member counts

// =======================================================================
// K1: h = x@W, xw = x@W_ind, s = leaky_relu(h@a_node), hn = h@a_gn
// grid 1024 blocks x 256 threads; each block handles 16 (b,n) rows
// =======================================================================
__global__ void k_h(const float* __restrict__ x,
                    const float* __restrict__ W,
                    const float* __restrict__ Wi,
                    const float* __restrict__ a_node,
                    const float* __restrict__ a_gn)
{
    __shared__ float sW[FF * FF];
    __shared__ float sWi[FF * FF];
    __shared__ float sx[16 * FF];
    __shared__ float red[256];

    int tid = threadIdx.x;
    for (int i = tid; i < FF * FF; i += 256) { sW[i] = W[i]; sWi[i] = Wi[i]; }

    long pbase = (long)blockIdx.x * 16;           // pair index base (pair = b*N + n)
    for (int i = tid; i < 16 * FF; i += 256)
        sx[i] = x[(pbase + (i >> 6)) * FF + (i & 63)];
    __syncthreads();

    int f = tid & 63, grp = tid >> 6;             // 4 groups of 64 threads
    for (int it = 0; it < 4; ++it) {
        int nl = grp * 4 + it;                     // local row 0..15
        long pair = pbase + nl;
        const float* xr = &sx[nl * FF];
        float hv = 0.f, xv = 0.f;
        #pragma unroll
        for (int k = 0; k < FF; ++k) {
            float xk = xr[k];
            hv += xk * sW[k * FF + f];
            xv += xk * sWi[k * FF + f];
        }
        g_h[pair * FF + f]  = hv;
        g_xw[pair * FF + f] = xv;

        // s = leaky_relu(h . a_node)
        red[tid] = hv * a_node[f];
        __syncthreads();
        for (int off = 32; off > 0; off >>= 1) {
            if (f < off) red[tid] += red[tid + off];
            __syncthreads();
        }
        if (f == 0) {
            float sv = red[grp * 64];
            g_s[pair] = (sv >= 0.f) ? sv : 0.2f * sv;
        }
        __syncthreads();

        // hn = h . a_gn
        red[tid] = hv * a_gn[f];
        __syncthreads();
        for (int off = 32; off > 0; off >>= 1) {
            if (f < off) red[tid] += red[tid + off];
            __syncthreads();
        }
        if (f == 0) g_hn[pair] = red[grp * 64];
        __syncthreads();
    }
}

// =======================================================================
// K2: per-edge member lists (deterministic ballot compaction)
// grid 64 blocks x 32 threads (one warp per edge)
// =======================================================================
__global__ void k_emem(const float* __restrict__ H)
{
    int e = blockIdx.x, lane = threadIdx.x;
    int cnt = 0;
    for (int base = 0; base < NN; base += 32) {
        int n = base + lane;
        bool m = H[n * EE + e] > 0.f;
        unsigned bm = __ballot_sync(0xffffffffu, m);
        if (m) g_emem[e * NN + cnt + __popc(bm & ((1u << lane) - 1u))] = n;
        cnt += __popc(bm);
    }
    if (lane == 0) g_ecnt[e] = cnt;
}

// =======================================================================
// K3: per (b,e): member softmax -> agg, ge, se
// grid (E, B) x 128 threads
// =======================================================================
__global__ void k_edge(const float* __restrict__ a_ge,
                       const float* __restrict__ fcW,
                       const float* __restrict__ fcb,
                       const float* __restrict__ av)
{
    int e = blockIdx.x, b = blockIdx.y, tid = threadIdx.x;
    int M = g_ecnt[e];

    __shared__ float red[128];
    __shared__ float sw[1024];
    __shared__ float sagg[FF];
    __shared__ float selu[FF];

    if (M == 0) {   // empty hyperedge: contributes nothing downstream
        if (tid < FF) g_agg[((b * EE) + e) * FF + tid] = 0.f;
        if (tid == 0) { g_ge[b * EE + e] = 0.f; g_se[b * EE + e] = 0.f; }
        return;
    }

    const int*   mem = &g_emem[e * NN];
    const float* sb  = &g_s[b * NN];

    // max over member scores
    float mx = -1e30f;
    for (int i = tid; i < M; i += 128) mx = fmaxf(mx, sb[mem[i]]);
    red[tid] = mx; __syncthreads();
    for (int off = 64; off > 0; off >>= 1) {
        if (tid < off) red[tid] = fmaxf(red[tid], red[tid + off]);
        __syncthreads();
    }
    float maxv = red[0];
    __syncthreads();

    // sum of exp; stash weights
    float ps = 0.f;
    for (int i = tid; i < M; i += 128) {
        float w = expf(sb[mem[i]] - maxv);
        if (i < 1024) sw[i] = w;
        ps += w;
    }
    red[tid] = ps; __syncthreads();
    for (int off = 64; off > 0; off >>= 1) {
        if (tid < off) red[tid] += red[tid + off];
        __syncthreads();
    }
    float inv = 1.f / red[0];
    __syncthreads();

    // agg[f] = sum_i alpha_i h[b, m_i, f]
    if (tid < FF) {
        float acc = 0.f;
        for (int i = 0; i < M; ++i) {
            float w = (i < 1024) ? sw[i] : expf(sb[mem[i]] - maxv);
            acc += w * g_h[((long)b * NN + mem[i]) * FF + tid];
        }
        acc *= inv;
        sagg[tid] = acc;
        g_agg[((b * EE) + e) * FF + tid] = acc;
        selu[tid] = (acc > 0.f) ? acc : expm1f(acc);
    }
    __syncthreads();

    // ge = agg . a_ge
    red[tid] = (tid < FF) ? sagg[tid] * a_ge[tid] : 0.f;
    __syncthreads();
    for (int off = 64; off > 0; off >>= 1) {
        if (tid < off) red[tid] += red[tid + off];
        __syncthreads();
    }
    if (tid == 0) g_ge[b * EE + e] = red[0];
    __syncthreads();

    // se = tanh(elu(agg) @ fcW + fcb) . av
    float z = fcb[tid];
    #pragma unroll
    for (int f2 = 0; f2 < FF; ++f2) z += selu[f2] * fcW[f2 * FC + tid];
    red[tid] = av[tid] * tanhf(z);
    __syncthreads();
    for (int off = 64; off > 0; off >>= 1) {
        if (tid < off) red[tid] += red[tid + off];
        __syncthreads();
    }
    if (tid == 0) g_se[b * EE + e] = red[0];
}

// =======================================================================
// K4: industry[b,n,f] = (1/deg_n) * sum_{m in nbr(n)} xw[b,m,f]
// grid 2048 blocks (node) x 512 threads (b*64+f)
// =======================================================================
__global__ void k_ind(const float* __restrict__ adj)
{
    int n = blockIdx.x, tid = threadIdx.x;
    int wid = tid >> 5, lane = tid & 31;
    int b = tid >> 6, f = tid & 63;

    __shared__ int wcnt[16], woff[16], list[512];
    __shared__ int schunk;

    float acc = 0.f;
    int deg = 0;
    const float* row = adj + (long)n * NN;
    const float* xwb = g_xw + (long)b * NN * FF + f;

    for (int base = 0; base < NN; base += 512) {
        int m = base + tid;
        bool p = row[m] > 0.f;
        unsigned bm = __ballot_sync(0xffffffffu, p);
        if (lane == 0) wcnt[wid] = __popc(bm);
        __syncthreads();
        if (tid == 0) {
            int t = 0;
            for (int w2 = 0; w2 < 16; ++w2) { woff[w2] = t; t += wcnt[w2]; }
            schunk = t;
        }
        __syncthreads();
        if (p) list[woff[wid] + __popc(bm & ((1u << lane) - 1u))] = m;
        __syncthreads();
        int cc = schunk;
        for (int i = 0; i < cc; ++i) acc += xwb[(long)list[i] * FF];
        deg += cc;
        __syncthreads();
    }
    float d = (float)deg;
    if (d < 1.f) d = 1.f;
    g_ind[((long)b * NN + n) * FF + f] = acc / d;
}

// =======================================================================
// K5: per (b,n): coefs1, gated-elu g, pair attention, output
// grid 2048 blocks x 128 threads; 8 nodes per block (fcW amortized in smem)
// =======================================================================
__global__ void k_final(const float* __restrict__ Hm,
                        const float* __restrict__ fcW,
                        const float* __restrict__ fcb,
                        const float* __restrict__ av,
                        float* __restrict__ out)
{
    __shared__ float sfc[FF * FC];     // 32 KB
    __shared__ float sind[FF], sh[FF], sg[FF];
    __shared__ float sc[EE], sbeta[EE];
    __shared__ float red[128];
    __shared__ float sfcb[FC], sav[FC];
    __shared__ float ssc[2];

    int tid = threadIdx.x;
    for (int i = tid; i < FF * FC; i += 128) sfc[i] = fcW[i];
    sfcb[tid] = fcb[tid];
    sav[tid]  = av[tid];
    __syncthreads();

    for (int it = 0; it < 8; ++it) {
        long pair = (long)blockIdx.x * 8 + it;
        int b = (int)(pair >> 11), n = (int)(pair & 2047);

        if (tid < FF) {
            sind[tid] = g_ind[pair * FF + tid];
            sh[tid]   = g_h[pair * FF + tid];
        }
        float hnv = g_hn[pair];

        // coefs1: masked softmax over this node's member edges
        float sev = -1e30f;
        bool mem = false;
        if (tid < EE) {
            mem = Hm[n * EE + tid] > 0.f;
            if (mem) sev = g_se[b * EE + tid];
        }
        red[tid] = (tid < EE) ? sev : -1e30f;
        __syncthreads();
        for (int off = 64; off > 0; off >>= 1) {
            if (tid < off) red[tid] = fmaxf(red[tid], red[tid + off]);
            __syncthreads();
        }
        float maxv = red[0];
        __syncthreads();
        float ex = (tid < EE && mem) ? expf(sev - maxv) : 0.f;
        red[tid] = ex;
        __syncthreads();
        for (int off = 64; off > 0; off >>= 1) {
            if (tid < off) red[tid] += red[tid + off];
            __syncthreads();
        }
        float ssum = red[0];
        __syncthreads();
        if (tid < EE) {
            sc[tid] = ex / ssum;   // exactly 0 for non-members
            sbeta[tid] = mem ? 1.f / (1.f + expf(-(hnv + g_ge[b * EE + tid]))) : 0.f;
        }
        __syncthreads();

        // g[f] = sum_e c_e * elu(beta*h + (1-beta)*agg)
        if (tid < FF) {
            float hf = sh[tid];
            float gacc = 0.f;
            for (int e = 0; e < EE; ++e) {
                float c = sc[e];
                if (c != 0.f) {    // warp-uniform branch
                    float bt = sbeta[e];
                    float v = bt * hf + (1.f - bt) * g_agg[((b << 6) + e) * FF + tid];
                    gacc += c * ((v > 0.f) ? v : expm1f(v));
                }
            }
            sg[tid] = gacc;
        }
        __syncthreads();

        // pair attention scores
        float z1 = sfcb[tid], z2 = sfcb[tid];
        #pragma unroll
        for (int f2 = 0; f2 < FF; ++f2) {
            float w = sfc[f2 * FC + tid];
            z1 += sind[f2] * w;
            z2 += sg[f2] * w;
        }
        red[tid] = sav[tid] * tanhf(z1);
        __syncthreads();
        for (int off = 64; off > 0; off >>= 1) {
            if (tid < off) red[tid] += red[tid + off];
            __syncthreads();
        }
        if (tid == 0) ssc[0] = red[0];
        __syncthreads();
        red[tid] = sav[tid] * tanhf(z2);
        __syncthreads();
        for (int off = 64; off > 0; off >>= 1) {
            if (tid < off) red[tid] += red[tid + off];
            __syncthreads();
        }
        if (tid == 0) ssc[1] = red[0];
        __syncthreads();

        float s1 = ssc[0], s2 = ssc[1];
        float m2 = fmaxf(s1, s2);
        float e1 = expf(s1 - m2), e2 = expf(s2 - m2);
        float c1 = e1 / (e1 + e2);
        if (tid < FF)
            out[pair * FF + tid] = c1 * sind[tid] + (1.f - c1) * sg[tid];
        __syncthreads();
    }
}

// =======================================================================
// launcher
// =======================================================================
extern "C" void kernel_launch(void* const* d_in, const int* in_sizes, int n_in,
                              void* d_out, int out_size)
{
    const float* x   = (const float*)d_in[0];
    const float* H   = (const float*)d_in[1];
    const float* adj = (const float*)d_in[2];
    // nhid (scalar) may or may not occupy a slot; detect by size
    int wb = (n_in >= 12 && in_sizes[3] == 1) ? 4 : 3;
    const float* W      = (const float*)d_in[wb + 0];
    const float* W_ind  = (const float*)d_in[wb + 1];
    const float* a_node = (const float*)d_in[wb + 2];
    const float* a_gn   = (const float*)d_in[wb + 3];
    const float* a_ge   = (const float*)d_in[wb + 4];
    const float* fcW    = (const float*)d_in[wb + 5];
    const float* fcb    = (const float*)d_in[wb + 6];
    const float* av     = (const float*)d_in[wb + 7];
    float* out = (float*)d_out;

    k_h<<<(BB * NN) / 16, 256>>>(x, W, W_ind, a_node, a_gn);
    k_emem<<<EE, 32>>>(H);
    k_edge<<<dim3(EE, BB), 128>>>(a_ge, fcW, fcb, av);
    k_ind<<<NN, 512>>>(adj);
    k_final<<<(BB * NN) / 8, 128>>>(H, fcW, fcb, av, out);
}

// round 3
// speedup vs baseline: 1.8946x; 1.8946x over previous
#include <cuda_runtime.h>
#include <cuda_bf16.h>

// Problem constants (HGAT_9543417332149): B=8, N=2048, E=64, F=NH=64, FC=2*NH=128
#define BB 8
#define NN 2048
#define EE 64
#define FF 64
#define FC 128

// -------- device scratch (no allocations allowed) --------
__device__ float g_h[BB * NN * FF];     // h = x @ W
__device__ float g_xw[BB * NN * FF];    // x @ W_ind
__device__ float g_s[BB * NN];          // leaky_relu(h @ a_node)
__device__ float g_hn[BB * NN];         // h @ a_gn
__device__ float g_agg[BB * EE * FF];   // hyperedge embedding (raw, pre-elu)
__device__ float g_ge[BB * EE];         // agg @ a_ge
__device__ float g_se[BB * EE];         // edge scores from elu(agg)
__device__ float g_ind[BB * NN * FF];   // industry features
__device__ int   g_emem[EE * NN];       // per-edge member node lists
__device__ int   g_ecnt[EE];            // per-edge member counts

// =======================================================================
// K1: h = x@W, xw = x@W_ind, s = leaky_relu(x @ (W@a_node)), hn = x@(W@a_gn)
// grid 1024 blocks x 256 threads; 16 rows per block. Only 2 barriers.
// =======================================================================
__global__ __launch_bounds__(256) void k_h(const float* __restrict__ x,
                                           const float* __restrict__ W,
                                           const float* __restrict__ Wi,
                                           const float* __restrict__ a_node,
                                           const float* __restrict__ a_gn)
{
    __shared__ float sW[FF * 65];    // stride-65 pad: conflict-free both axes
    __shared__ float sWi[FF * 65];
    __shared__ float sx[16 * 65];
    __shared__ float sa_n[FF], sa_g[FF];
    __shared__ float sp_n[FF], sp_g[FF];

    int tid = threadIdx.x;
    for (int i = tid; i < FF * FF; i += 256) {
        int k = i >> 6, f = i & 63;
        sW[k * 65 + f]  = W[i];
        sWi[k * 65 + f] = Wi[i];
    }
    if (tid < FF) { sa_n[tid] = a_node[tid]; sa_g[tid] = a_gn[tid]; }

    long pbase = (long)blockIdx.x * 16;
    for (int i = tid; i < 16 * FF; i += 256)
        sx[(i >> 6) * 65 + (i & 63)] = x[(pbase + (i >> 6)) * FF + (i & 63)];
    __syncthreads();

    // p_node[k] = W[k,:].a_node ; p_gn[k] = W[k,:].a_gn
    if (tid < 64) {
        int k = tid; float p = 0.f;
        #pragma unroll
        for (int f = 0; f < FF; ++f) p += sW[k * 65 + f] * sa_n[f];
        sp_n[k] = p;
    } else if (tid < 128) {
        int k = tid - 64; float p = 0.f;
        #pragma unroll
        for (int f = 0; f < FF; ++f) p += sW[k * 65 + f] * sa_g[f];
        sp_g[k] = p;
    }
    __syncthreads();

    int f = tid & 63, grp = tid >> 6;
    #pragma unroll
    for (int it = 0; it < 4; ++it) {
        int nl = grp * 4 + it;
        long pair = pbase + nl;
        const float* xr = &sx[nl * 65];
        float hv = 0.f, xv = 0.f;
        #pragma unroll
        for (int k = 0; k < FF; ++k) {
            float xk = xr[k];
            hv += xk * sW[k * 65 + f];
            xv += xk * sWi[k * 65 + f];
        }
        g_h[pair * FF + f]  = hv;
        g_xw[pair * FF + f] = xv;
    }

    // s = lrelu(x.p_node), hn = x.p_gn  (16+16 threads, serial 64-FMA dots)
    if (tid < 16) {
        int r = tid; long pair = pbase + r;
        float s = 0.f;
        #pragma unroll
        for (int k = 0; k < FF; ++k) s += sx[r * 65 + k] * sp_n[k];
        g_s[pair] = (s >= 0.f) ? s : 0.2f * s;
    } else if (tid < 32) {
        int r = tid - 16; long pair = pbase + r;
        float hn = 0.f;
        #pragma unroll
        for (int k = 0; k < FF; ++k) hn += sx[r * 65 + k] * sp_g[k];
        g_hn[pair] = hn;
    }
}

// =======================================================================
// K2: per-edge member lists (deterministic ballot compaction)
// =======================================================================
__global__ void k_emem(const float* __restrict__ H)
{
    int e = blockIdx.x, lane = threadIdx.x;
    int cnt = 0;
    for (int base = 0; base < NN; base += 32) {
        int n = base + lane;
        bool m = H[n * EE + e] > 0.f;
        unsigned bm = __ballot_sync(0xffffffffu, m);
        if (m) g_emem[e * NN + cnt + __popc(bm & ((1u << lane) - 1u))] = n;
        cnt += __popc(bm);
    }
    __syncwarp();
    if (lane == 0) g_ecnt[e] = cnt;
}

// =======================================================================
// K3: per (b,e): member softmax -> agg, ge, se. 256 threads.
// =======================================================================
__global__ __launch_bounds__(256) void k_edge(const float* __restrict__ a_ge,
                                              const float* __restrict__ fcW,
                                              const float* __restrict__ fcb,
                                              const float* __restrict__ av)
{
    int e = blockIdx.x, b = blockIdx.y, tid = threadIdx.x;
    int wid = tid >> 5, lane = tid & 31;
    int M = g_ecnt[e];

    __shared__ float red8[8];
    __shared__ float swv[512];
    __shared__ float sagg[FF], selu[FF];
    __shared__ float comb[256];

    if (M == 0) {
        if (tid < FF) g_agg[((b * EE) + e) * FF + tid] = 0.f;
        if (tid == 0) { g_ge[b * EE + e] = 0.f; g_se[b * EE + e] = 0.f; }
        return;
    }

    const int*   mem = &g_emem[e * NN];
    const float* sb  = &g_s[b * NN];

    // ---- max over member scores ----
    float mx = -1e30f;
    for (int i = tid; i < M; i += 256) mx = fmaxf(mx, sb[mem[i]]);
    #pragma unroll
    for (int o = 16; o; o >>= 1) mx = fmaxf(mx, __shfl_xor_sync(0xffffffffu, mx, o));
    if (lane == 0) red8[wid] = mx;
    __syncthreads();
    float maxv = red8[0];
    #pragma unroll
    for (int w2 = 1; w2 < 8; ++w2) maxv = fmaxf(maxv, red8[w2]);
    __syncthreads();

    // ---- sum of exp; stash weights ----
    float ps = 0.f;
    for (int i = tid; i < M; i += 256) {
        float w = expf(sb[mem[i]] - maxv);
        if (i < 512) swv[i] = w;
        ps += w;
    }
    #pragma unroll
    for (int o = 16; o; o >>= 1) ps += __shfl_xor_sync(0xffffffffu, ps, o);
    if (lane == 0) red8[wid] = ps;
    __syncthreads();
    float ssum = 0.f;
    #pragma unroll
    for (int w2 = 0; w2 < 8; ++w2) ssum += red8[w2];
    float inv = 1.f / ssum;

    // ---- agg[f] = sum_i alpha_i h[b, m_i, f] (4-way member split) ----
    int f = tid & 63, q = tid >> 6;
    float acc = 0.f;
    for (int i = q; i < M; i += 4) {
        float w = (i < 512) ? swv[i] : expf(sb[mem[i]] - maxv);
        acc += w * g_h[((long)b * NN + mem[i]) * FF + f];
    }
    comb[tid] = acc;
    __syncthreads();
    if (tid < FF) {
        float a = (comb[tid] + comb[tid + 64] + comb[tid + 128] + comb[tid + 192]) * inv;
        sagg[tid] = a;
        g_agg[((b * EE) + e) * FF + tid] = a;
        selu[tid] = (a > 0.f) ? a : expm1f(a);
    }
    __syncthreads();

    // ---- ge = agg . a_ge ----
    float pg = (tid < FF) ? sagg[tid] * a_ge[tid] : 0.f;
    #pragma unroll
    for (int o = 16; o; o >>= 1) pg += __shfl_xor_sync(0xffffffffu, pg, o);
    if (lane == 0) red8[wid] = pg;
    __syncthreads();
    if (tid == 0) g_ge[b * EE + e] = red8[0] + red8[1];

    // ---- se = tanh(elu(agg) @ fcW + fcb) . av  (threads 0..127) ----
    float pv = 0.f;
    if (tid < FC) {
        float z = fcb[tid];
        #pragma unroll
        for (int f2 = 0; f2 < FF; ++f2) z += selu[f2] * __ldg(&fcW[f2 * FC + tid]);
        pv = av[tid] * tanhf(z);
    }
    #pragma unroll
    for (int o = 16; o; o >>= 1) pv += __shfl_xor_sync(0xffffffffu, pv, o);
    __syncthreads();
    if (lane == 0) red8[wid] = pv;
    __syncthreads();
    if (tid == 0) g_se[b * EE + e] = red8[0] + red8[1] + red8[2] + red8[3];
}

// =======================================================================
// K4: industry. Per-warp ballot compaction into per-warp segments.
// ONE block barrier. grid 2048 x 512 threads (b*64+f).
// =======================================================================
__global__ __launch_bounds__(512) void k_ind(const float* __restrict__ adj)
{
    int n = blockIdx.x, tid = threadIdx.x;
    int wid = tid >> 5, lane = tid & 31;
    int b = tid >> 6, f = tid & 63;

    __shared__ int list[2048];
    __shared__ int wcnt[16];

    const float* row = adj + (long)n * NN;

    // warp wid scans m in [wid*128, wid*128+128)
    int base = wid * 128;
    int cnt = 0;
    #pragma unroll
    for (int j = 0; j < 4; ++j) {
        int m = base + j * 32 + lane;
        bool p = row[m] > 0.f;
        unsigned bm = __ballot_sync(0xffffffffu, p);
        if (p) list[base + cnt + __popc(bm & ((1u << lane) - 1u))] = m;
        cnt += __popc(bm);
    }
    if (lane == 0) wcnt[wid] = cnt;
    __syncthreads();

    float acc0 = 0.f, acc1 = 0.f;
    int deg = 0;
    const float* xwb = g_xw + (long)b * NN * FF + f;
    #pragma unroll 1
    for (int w2 = 0; w2 < 16; ++w2) {
        int cw = wcnt[w2];
        const int* lw = &list[w2 * 128];
        int i = 0;
        for (; i + 1 < cw; i += 2) {
            acc0 += xwb[(long)lw[i] * FF];
            acc1 += xwb[(long)lw[i + 1] * FF];
        }
        if (i < cw) acc0 += xwb[(long)lw[i] * FF];
        deg += cw;
    }
    float d = (deg < 1) ? 1.f : (float)deg;
    g_ind[((long)b * NN + n) * FF + f] = (acc0 + acc1) / d;
}

// =======================================================================
// K5: one WARP per (b,n) pair. 256 threads = 8 pairs/block, fcW in smem.
// Zero block barriers after weight load; all reductions are shuffles.
// =======================================================================
__global__ __launch_bounds__(256) void k_final(const float* __restrict__ Hm,
                                               const float* __restrict__ fcW,
                                               const float* __restrict__ fcb,
                                               const float* __restrict__ av,
                                               float* __restrict__ out)
{
    __shared__ float sfc[FF * FC];     // 32 KB
    __shared__ float sfcb[FC], sav[FC];
    __shared__ float swi[8][FF];       // per-warp industry vector
    __shared__ float swg[8][FF];       // per-warp g vector

    int tid = threadIdx.x, w = tid >> 5, lane = tid & 31;
    for (int i = tid; i < FF * FC; i += 256) sfc[i] = fcW[i];
    if (tid < FC) { sfcb[tid] = fcb[tid]; sav[tid] = av[tid]; }
    __syncthreads();

    long pair = (long)blockIdx.x * 8 + w;
    int b = (int)(pair >> 11), n = (int)(pair & 2047);
    int f0 = lane, f1 = lane + 32;

    float ind0 = g_ind[pair * FF + f0], ind1 = g_ind[pair * FF + f1];
    float h0   = g_h[pair * FF + f0],   h1   = g_h[pair * FF + f1];
    float hnv  = g_hn[pair];

    // ---- coefs1: masked softmax over this node's member edges (lane owns e0,e1)
    bool m0 = Hm[(long)n * EE + lane] > 0.f;
    bool m1 = Hm[(long)n * EE + lane + 32] > 0.f;
    float se0 = m0 ? g_se[b * EE + lane]      : -1e30f;
    float se1 = m1 ? g_se[b * EE + lane + 32] : -1e30f;
    float mx = fmaxf(se0, se1);
    #pragma unroll
    for (int o = 16; o; o >>= 1) mx = fmaxf(mx, __shfl_xor_sync(0xffffffffu, mx, o));
    float ex0 = m0 ? expf(se0 - mx) : 0.f;
    float ex1 = m1 ? expf(se1 - mx) : 0.f;
    float sum = ex0 + ex1;
    #pragma unroll
    for (int o = 16; o; o >>= 1) sum += __shfl_xor_sync(0xffffffffu, sum, o);
    float inv = 1.f / sum;
    float c0 = ex0 * inv, c1 = ex1 * inv;
    float bt0 = m0 ? 1.f / (1.f + expf(-(hnv + g_ge[b * EE + lane])))      : 0.f;
    float bt1 = m1 ? 1.f / (1.f + expf(-(hnv + g_ge[b * EE + lane + 32]))) : 0.f;

    // ---- g[f] = sum_e c_e * elu(beta_e*h + (1-beta_e)*agg_e) ----
    float gv0 = 0.f, gv1 = 0.f;
    const float* aggb = g_agg + ((long)b * EE) * FF;
    #pragma unroll 1
    for (int e = 0; e < EE; ++e) {
        float ce = __shfl_sync(0xffffffffu, (e < 32) ? c0 : c1, e & 31);
        if (ce != 0.f) {   // warp-uniform (~2.9 of 64 taken)
            float bt = __shfl_sync(0xffffffffu, (e < 32) ? bt0 : bt1, e & 31);
            float a0 = aggb[e * FF + f0], a1 = aggb[e * FF + f1];
            float v0 = bt * h0 + (1.f - bt) * a0;
            float v1 = bt * h1 + (1.f - bt) * a1;
            gv0 += ce * ((v0 > 0.f) ? v0 : expm1f(v0));
            gv1 += ce * ((v1 > 0.f) ? v1 : expm1f(v1));
        }
    }

    swi[w][f0] = ind0; swi[w][f1] = ind1;
    swg[w][f0] = gv0;  swg[w][f1] = gv1;
    __syncwarp();

    // ---- pair attention: two 128-col tanh matvecs, lane owns 4 contiguous cols
    float z1[4], z2[4];
    #pragma unroll
    for (int j = 0; j < 4; ++j) { z1[j] = sfcb[lane * 4 + j]; z2[j] = z1[j]; }
    #pragma unroll 4
    for (int f2 = 0; f2 < FF; ++f2) {
        float iv = swi[w][f2], gg = swg[w][f2];
        float4 wv = *(const float4*)&sfc[f2 * FC + lane * 4];  // LDS.128
        z1[0] += iv * wv.x; z1[1] += iv * wv.y; z1[2] += iv * wv.z; z1[3] += iv * wv.w;
        z2[0] += gg * wv.x; z2[1] += gg * wv.y; z2[2] += gg * wv.z; z2[3] += gg * wv.w;
    }
    float p1 = 0.f, p2 = 0.f;
    #pragma unroll
    for (int j = 0; j < 4; ++j) {
        float a = sav[lane * 4 + j];
        p1 += a * tanhf(z1[j]);
        p2 += a * tanhf(z2[j]);
    }
    #pragma unroll
    for (int o = 16; o; o >>= 1) {
        p1 += __shfl_xor_sync(0xffffffffu, p1, o);
        p2 += __shfl_xor_sync(0xffffffffu, p2, o);
    }

    float mm = fmaxf(p1, p2);
    float q1 = expf(p1 - mm), q2 = expf(p2 - mm);
    float cc = q1 / (q1 + q2);
    out[pair * FF + f0] = cc * ind0 + (1.f - cc) * gv0;
    out[pair * FF + f1] = cc * ind1 + (1.f - cc) * gv1;
}

// =======================================================================
// launcher
// =======================================================================
extern "C" void kernel_launch(void* const* d_in, const int* in_sizes, int n_in,
                              void* d_out, int out_size)
{
    const float* x   = (const float*)d_in[0];
    const float* H   = (const float*)d_in[1];
    const float* adj = (const float*)d_in[2];
    int wb = (n_in >= 12 && in_sizes[3] == 1) ? 4 : 3;
    const float* W      = (const float*)d_in[wb + 0];
    const float* W_ind  = (const float*)d_in[wb + 1];
    const float* a_node = (const float*)d_in[wb + 2];
    const float* a_gn   = (const float*)d_in[wb + 3];
    const float* a_ge   = (const float*)d_in[wb + 4];
    const float* fcW    = (const float*)d_in[wb + 5];
    const float* fcb    = (const float*)d_in[wb + 6];
    const float* av     = (const float*)d_in[wb + 7];
    float* out = (float*)d_out;

    k_h<<<(BB * NN) / 16, 256>>>(x, W, W_ind, a_node, a_gn);
    k_emem<<<EE, 32>>>(H);
    k_edge<<<dim3(EE, BB), 256>>>(a_ge, fcW, fcb, av);
    k_ind<<<NN, 512>>>(adj);
    k_final<<<(BB * NN) / 8, 256>>>(H, fcW, fcb, av, out);
}

// round 5
// speedup vs baseline: 2.1930x; 1.1575x over previous
#include <cuda_runtime.h>
#include <cuda_bf16.h>

// Problem constants (HGAT_9543417332149): B=8, N=2048, E=64, F=NH=64, FC=2*NH=128
#define BB 8
#define NN 2048
#define EE 64
#define FF 64
#define FC 128

// -------- device scratch (no allocations allowed) --------
__device__ float g_h[BB * NN * FF];     // h = x @ W
__device__ float g_xw[BB * NN * FF];    // x @ W_ind
__device__ float g_s[BB * NN];          // leaky_relu(h @ a_node)
__device__ float g_hn[BB * NN];         // h @ a_gn
__device__ float g_agg[BB * EE * FF];   // hyperedge embedding (raw, pre-elu)
__device__ float g_ge[BB * EE];         // agg @ a_ge
__device__ float g_se[BB * EE];         // edge scores from elu(agg)
__device__ float g_ind[BB * NN * FF];   // industry features
__device__ int   g_emem[EE * NN];       // per-edge member node lists
__device__ int   g_ecnt[EE];            // per-edge member counts

// =======================================================================
// K1 (fused): blocks 0..511  -> h/xw/s/hn for 32 rows each
//             blocks 512..519 -> per-edge member lists (1 warp / edge)
// =======================================================================
__global__ __launch_bounds__(256) void k_h_emem(const float* __restrict__ x,
                                                const float* __restrict__ H,
                                                const float* __restrict__ W,
                                                const float* __restrict__ Wi,
                                                const float* __restrict__ a_node,
                                                const float* __restrict__ a_gn)
{
    __shared__ float sW[FF * 65];    // stride-65 pad: conflict-free both axes
    __shared__ float sWi[FF * 65];
    __shared__ float sx[32 * 65];
    __shared__ float sa_n[FF], sa_g[FF];
    __shared__ float sp_n[FF], sp_g[FF];

    int tid = threadIdx.x;

    if (blockIdx.x >= 512) {
        // ---- member-list compaction: warp w handles edge ----
        int e = (int)(blockIdx.x - 512) * 8 + (tid >> 5);
        int lane = tid & 31;
        int cnt = 0;
        for (int base = 0; base < NN; base += 32) {
            int n = base + lane;
            bool m = H[n * EE + e] > 0.f;
            unsigned bm = __ballot_sync(0xffffffffu, m);
            if (m) g_emem[e * NN + cnt + __popc(bm & ((1u << lane) - 1u))] = n;
            cnt += __popc(bm);
        }
        if (lane == 0) g_ecnt[e] = cnt;
        return;
    }

    for (int i = tid; i < FF * FF; i += 256) {
        int k = i >> 6, f = i & 63;
        sW[k * 65 + f]  = W[i];
        sWi[k * 65 + f] = Wi[i];
    }
    if (tid < FF) { sa_n[tid] = a_node[tid]; sa_g[tid] = a_gn[tid]; }

    long pbase = (long)blockIdx.x * 32;
    for (int i = tid; i < 32 * FF; i += 256)
        sx[(i >> 6) * 65 + (i & 63)] = x[(pbase + (i >> 6)) * FF + (i & 63)];
    __syncthreads();

    // p_node[k] = W[k,:].a_node ; p_gn[k] = W[k,:].a_gn
    if (tid < 64) {
        int k = tid; float p = 0.f;
        #pragma unroll
        for (int f = 0; f < FF; ++f) p += sW[k * 65 + f] * sa_n[f];
        sp_n[k] = p;
    } else if (tid < 128) {
        int k = tid - 64; float p = 0.f;
        #pragma unroll
        for (int f = 0; f < FF; ++f) p += sW[k * 65 + f] * sa_g[f];
        sp_g[k] = p;
    }
    __syncthreads();

    int f = tid & 63, grp = tid >> 6;
    #pragma unroll
    for (int it = 0; it < 8; ++it) {
        int nl = grp * 8 + it;
        long pair = pbase + nl;
        const float* xr = &sx[nl * 65];
        float hv = 0.f, xv = 0.f;
        #pragma unroll
        for (int k = 0; k < FF; ++k) {
            float xk = xr[k];
            hv += xk * sW[k * 65 + f];
            xv += xk * sWi[k * 65 + f];
        }
        g_h[pair * FF + f]  = hv;
        g_xw[pair * FF + f] = xv;
    }

    // s = lrelu(x.p_node), hn = x.p_gn (32+32 threads, serial 64-FMA dots)
    if (tid < 32) {
        int r = tid; long pair = pbase + r;
        float s = 0.f;
        #pragma unroll
        for (int k = 0; k < FF; ++k) s += sx[r * 65 + k] * sp_n[k];
        g_s[pair] = (s >= 0.f) ? s : 0.2f * s;
    } else if (tid < 64) {
        int r = tid - 32; long pair = pbase + r;
        float hn = 0.f;
        #pragma unroll
        for (int k = 0; k < FF; ++k) hn += sx[r * 65 + k] * sp_g[k];
        g_hn[pair] = hn;
    }
}

// =======================================================================
// K2: industry. Per-warp ballot compaction -> contiguous list -> MLP-8 gather.
// grid 2048 x 512 threads (b*64+f).
// =======================================================================
__global__ __launch_bounds__(512) void k_ind(const float* __restrict__ adj)
{
    int n = blockIdx.x, tid = threadIdx.x;
    int wid = tid >> 5, lane = tid & 31;
    int b = tid >> 6, f = tid & 63;

    __shared__ int seg[2048];
    __shared__ int clist[2048];
    __shared__ int wcnt[16], woff[16];
    __shared__ int stot;

    const float* row = adj + (long)n * NN;

    // warp wid scans m in [wid*128, wid*128+128)
    int base = wid * 128;
    int cnt = 0;
    #pragma unroll
    for (int j = 0; j < 4; ++j) {
        int m = base + j * 32 + lane;
        bool p = row[m] > 0.f;
        unsigned bm = __ballot_sync(0xffffffffu, p);
        if (p) seg[base + cnt + __popc(bm & ((1u << lane) - 1u))] = m;
        cnt += __popc(bm);
    }
    if (lane == 0) wcnt[wid] = cnt;
    __syncthreads();

    // warp 0: exclusive prefix scan of the 16 counts
    if (tid < 32) {
        int c = (lane < 16) ? wcnt[lane] : 0;
        int s = c;
        #pragma unroll
        for (int o = 1; o < 16; o <<= 1) {
            int t = __shfl_up_sync(0xffffffffu, s, o);
            if (lane >= o) s += t;
        }
        if (lane < 16) woff[lane] = s - c;
        if (lane == 15) stot = s;
    }
    __syncthreads();

    // compact segments into contiguous clist
    {
        int c = wcnt[wid], o = woff[wid];
        for (int j = lane; j < c; j += 32) clist[o + j] = seg[wid * 128 + j];
    }
    __syncthreads();

    int total = stot;
    const float* xwb = g_xw + (long)b * NN * FF + f;

    float acc = 0.f;
    for (int i = 0; i < total; i += 8) {
        int   id[8];
        float v[8];
        #pragma unroll
        for (int j = 0; j < 8; ++j) id[j] = (i + j < total) ? clist[i + j] : clist[0];
        #pragma unroll
        for (int j = 0; j < 8; ++j) v[j] = xwb[(long)id[j] * FF];
        #pragma unroll
        for (int j = 0; j < 8; ++j) if (i + j < total) acc += v[j];
    }
    float d = (total < 1) ? 1.f : (float)total;
    g_ind[((long)b * NN + n) * FF + f] = acc / d;
}

// =======================================================================
// K3: per (b,e): member softmax -> agg, ge, se. 256 threads.
// =======================================================================
__global__ __launch_bounds__(256) void k_edge(const float* __restrict__ a_ge,
                                              const float* __restrict__ fcW,
                                              const float* __restrict__ fcb,
                                              const float* __restrict__ av)
{
    int e = blockIdx.x, b = blockIdx.y, tid = threadIdx.x;
    int wid = tid >> 5, lane = tid & 31;
    int M = g_ecnt[e];

    __shared__ float red8[8];
    __shared__ float swv[512];
    __shared__ float sagg[FF], selu[FF];
    __shared__ float comb[256];

    if (M == 0) {
        if (tid < FF) g_agg[((b * EE) + e) * FF + tid] = 0.f;
        if (tid == 0) { g_ge[b * EE + e] = 0.f; g_se[b * EE + e] = 0.f; }
        return;
    }

    const int*   mem = &g_emem[e * NN];
    const float* sb  = &g_s[b * NN];

    // ---- max over member scores ----
    float mx = -1e30f;
    for (int i = tid; i < M; i += 256) mx = fmaxf(mx, sb[mem[i]]);
    #pragma unroll
    for (int o = 16; o; o >>= 1) mx = fmaxf(mx, __shfl_xor_sync(0xffffffffu, mx, o));
    if (lane == 0) red8[wid] = mx;
    __syncthreads();
    float maxv = red8[0];
    #pragma unroll
    for (int w2 = 1; w2 < 8; ++w2) maxv = fmaxf(maxv, red8[w2]);
    __syncthreads();

    // ---- sum of exp; stash weights ----
    float ps = 0.f;
    for (int i = tid; i < M; i += 256) {
        float w = expf(sb[mem[i]] - maxv);
        if (i < 512) swv[i] = w;
        ps += w;
    }
    #pragma unroll
    for (int o = 16; o; o >>= 1) ps += __shfl_xor_sync(0xffffffffu, ps, o);
    if (lane == 0) red8[wid] = ps;
    __syncthreads();
    float ssum = 0.f;
    #pragma unroll
    for (int w2 = 0; w2 < 8; ++w2) ssum += red8[w2];
    float inv = 1.f / ssum;

    // ---- agg[f] = sum_i alpha_i h[b, m_i, f] (4-way member split) ----
    int f = tid & 63, q = tid >> 6;
    float acc = 0.f;
    for (int i = q; i < M; i += 4) {
        float w = (i < 512) ? swv[i] : expf(sb[mem[i]] - maxv);
        acc += w * g_h[((long)b * NN + mem[i]) * FF + f];
    }
    comb[tid] = acc;
    __syncthreads();
    if (tid < FF) {
        float a = (comb[tid] + comb[tid + 64] + comb[tid + 128] + comb[tid + 192]) * inv;
        sagg[tid] = a;
        g_agg[((b * EE) + e) * FF + tid] = a;
        selu[tid] = (a > 0.f) ? a : expm1f(a);
    }
    __syncthreads();

    // ---- ge = agg . a_ge ----
    float pg = (tid < FF) ? sagg[tid] * a_ge[tid] : 0.f;
    #pragma unroll
    for (int o = 16; o; o >>= 1) pg += __shfl_xor_sync(0xffffffffu, pg, o);
    if (lane == 0) red8[wid] = pg;
    __syncthreads();
    if (tid == 0) g_ge[b * EE + e] = red8[0] + red8[1];

    // ---- se = tanh(elu(agg) @ fcW + fcb) . av  (threads 0..127) ----
    float pv = 0.f;
    if (tid < FC) {
        float z = fcb[tid];
        #pragma unroll
        for (int f2 = 0; f2 < FF; ++f2) z += selu[f2] * __ldg(&fcW[f2 * FC + tid]);
        pv = av[tid] * tanhf(z);
    }
    #pragma unroll
    for (int o = 16; o; o >>= 1) pv += __shfl_xor_sync(0xffffffffu, pv, o);
    __syncthreads();
    if (lane == 0) red8[wid] = pv;
    __syncthreads();
    if (tid == 0) g_se[b * EE + e] = red8[0] + red8[1] + red8[2] + red8[3];
}

// =======================================================================
// K4: one WARP per (b,n) pair. 512 threads = 16 pairs/block.
// =======================================================================
__global__ __launch_bounds__(512) void k_final(const float* __restrict__ Hm,
                                               const float* __restrict__ fcW,
                                               const float* __restrict__ fcb,
                                               const float* __restrict__ av,
                                               float* __restrict__ out)
{
    __shared__ float sfc[FF * FC];     // 32 KB
    __shared__ float sfcb[FC], sav[FC];
    __shared__ float swi[16][FF];      // per-warp industry vector
    __shared__ float swg[16][FF];      // per-warp g vector

    int tid = threadIdx.x, w = tid >> 5, lane = tid & 31;
    for (int i = tid; i < FF * FC; i += 512) sfc[i] = fcW[i];
    if (tid < FC) { sfcb[tid] = fcb[tid]; sav[tid] = av[tid]; }
    __syncthreads();

    long pair = (long)blockIdx.x * 16 + w;
    int b = (int)(pair >> 11), n = (int)(pair & 2047);
    int f0 = lane, f1 = lane + 32;

    float ind0 = g_ind[pair * FF + f0], ind1 = g_ind[pair * FF + f1];
    float h0   = g_h[pair * FF + f0],   h1   = g_h[pair * FF + f1];
    float hnv  = g_hn[pair];

    // ---- coefs1: masked softmax over this node's member edges (lane owns e0,e1)
    bool m0 = Hm[(long)n * EE + lane] > 0.f;
    bool m1 = Hm[(long)n * EE + lane + 32] > 0.f;
    float se0 = m0 ? g_se[b * EE + lane]      : -1e30f;
    float se1 = m1 ? g_se[b * EE + lane + 32] : -1e30f;
    float mx = fmaxf(se0, se1);
    #pragma unroll
    for (int o = 16; o; o >>= 1) mx = fmaxf(mx, __shfl_xor_sync(0xffffffffu, mx, o));
    float ex0 = m0 ? expf(se0 - mx) : 0.f;
    float ex1 = m1 ? expf(se1 - mx) : 0.f;
    float sum = ex0 + ex1;
    #pragma unroll
    for (int o = 16; o; o >>= 1) sum += __shfl_xor_sync(0xffffffffu, sum, o);
    float inv = 1.f / sum;
    float c0 = ex0 * inv, c1 = ex1 * inv;
    float bt0 = m0 ? 1.f / (1.f + expf(-(hnv + g_ge[b * EE + lane])))      : 0.f;
    float bt1 = m1 ? 1.f / (1.f + expf(-(hnv + g_ge[b * EE + lane + 32]))) : 0.f;

    // ---- g[f] = sum_e c_e * elu(beta_e*h + (1-beta_e)*agg_e) ----
    float gv0 = 0.f, gv1 = 0.f;
    const float* aggb = g_agg + ((long)b * EE) * FF;
    #pragma unroll 1
    for (int e = 0; e < EE; ++e) {
        float ce = __shfl_sync(0xffffffffu, (e < 32) ? c0 : c1, e & 31);
        if (ce != 0.f) {   // warp-uniform (~2.9 of 64 taken)
            float bt = __shfl_sync(0xffffffffu, (e < 32) ? bt0 : bt1, e & 31);
            float a0 = aggb[e * FF + f0], a1 = aggb[e * FF + f1];
            float v0 = bt * h0 + (1.f - bt) * a0;
            float v1 = bt * h1 + (1.f - bt) * a1;
            gv0 += ce * ((v0 > 0.f) ? v0 : expm1f(v0));
            gv1 += ce * ((v1 > 0.f) ? v1 : expm1f(v1));
        }
    }

    swi[w][f0] = ind0; swi[w][f1] = ind1;
    swg[w][f0] = gv0;  swg[w][f1] = gv1;
    __syncwarp();

    // ---- pair attention: two 128-col tanh matvecs, lane owns 4 contiguous cols
    float z1[4], z2[4];
    #pragma unroll
    for (int j = 0; j < 4; ++j) { z1[j] = sfcb[lane * 4 + j]; z2[j] = z1[j]; }
    #pragma unroll 4
    for (int f2 = 0; f2 < FF; ++f2) {
        float iv = swi[w][f2], gg = swg[w][f2];
        float4 wv = *(const float4*)&sfc[f2 * FC + lane * 4];  // LDS.128
        z1[0] += iv * wv.x; z1[1] += iv * wv.y; z1[2] += iv * wv.z; z1[3] += iv * wv.w;
        z2[0] += gg * wv.x; z2[1] += gg * wv.y; z2[2] += gg * wv.z; z2[3] += gg * wv.w;
    }
    float p1 = 0.f, p2 = 0.f;
    #pragma unroll
    for (int j = 0; j < 4; ++j) {
        float a = sav[lane * 4 + j];
        p1 += a * tanhf(z1[j]);
        p2 += a * tanhf(z2[j]);
    }
    #pragma unroll
    for (int o = 16; o; o >>= 1) {
        p1 += __shfl_xor_sync(0xffffffffu, p1, o);
        p2 += __shfl_xor_sync(0xffffffffu, p2, o);
    }

    float mm = fmaxf(p1, p2);
    float q1 = expf(p1 - mm), q2 = expf(p2 - mm);
    float cc = q1 / (q1 + q2);
    out[pair * FF + f0] = cc * ind0 + (1.f - cc) * gv0;
    out[pair * FF + f1] = cc * ind1 + (1.f - cc) * gv1;
}

// =======================================================================
// launcher
// =======================================================================
extern "C" void kernel_launch(void* const* d_in, const int* in_sizes, int n_in,
                              void* d_out, int out_size)
{
    const float* x   = (const float*)d_in[0];
    const float* H   = (const float*)d_in[1];
    const float* adj = (const float*)d_in[2];
    int wb = (n_in >= 12 && in_sizes[3] == 1) ? 4 : 3;
    const float* W      = (const float*)d_in[wb + 0];
    const float* W_ind  = (const float*)d_in[wb + 1];
    const float* a_node = (const float*)d_in[wb + 2];
    const float* a_gn   = (const float*)d_in[wb + 3];
    const float* a_ge   = (const float*)d_in[wb + 4];
    const float* fcW    = (const float*)d_in[wb + 5];
    const float* fcb    = (const float*)d_in[wb + 6];
    const float* av     = (const float*)d_in[wb + 7];
    float* out = (float*)d_out;

    k_h_emem<<<520, 256>>>(x, H, W, W_ind, a_node, a_gn);
    k_ind<<<NN, 512>>>(adj);
    k_edge<<<dim3(EE, BB), 256>>>(a_ge, fcW, fcb, av);
    k_final<<<(BB * NN) / 16, 512>>>(H, fcW, fcb, av, out);
}

// round 6
// speedup vs baseline: 2.5449x; 1.1605x over previous
#include <cuda_runtime.h>
#include <cuda_bf16.h>

// Problem constants (HGAT_9543417332149): B=8, N=2048, E=64, F=NH=64, FC=2*NH=128
#define BB 8
#define NN 2048
#define EE 64
#define FF 64
#define FC 128

// -------- device scratch (no allocations allowed) --------
__device__ float g_h[BB * NN * FF];     // h = x @ W
__device__ float g_xw[BB * NN * FF];    // x @ W_ind
__device__ float g_s[BB * NN];          // leaky_relu(h @ a_node)
__device__ float g_hn[BB * NN];         // h @ a_gn
__device__ float g_agg[BB * EE * FF];   // hyperedge embedding (raw, pre-elu)
__device__ float g_ge[BB * EE];         // agg @ a_ge
__device__ float g_se[BB * EE];         // edge scores from elu(agg)
__device__ float g_ind[BB * NN * FF];   // industry features
__device__ int   g_emem[EE * NN];       // per-edge member node lists
__device__ int   g_ecnt[EE];            // per-edge member counts

// fast tanh: 1 - 2/(e^{2x}+1); clamp keeps __fdividef divisor finite.
// |err| ~1e-6 (vs 1e-3 tolerance); saturates correctly at +-1.
__device__ __forceinline__ float ftanh(float x)
{
    x = fminf(fmaxf(x, -10.f), 10.f);
    float e = __expf(2.f * x);
    return 1.f - __fdividef(2.f, e + 1.f);
}

// =======================================================================
// K1 (fused): blocks 0..511  -> h/xw/s/hn for 32 rows each
//             blocks 512..519 -> per-edge member lists (1 warp / edge)
// =======================================================================
__global__ __launch_bounds__(256) void k_h_emem(const float* __restrict__ x,
                                                const float* __restrict__ H,
                                                const float* __restrict__ W,
                                                const float* __restrict__ Wi,
                                                const float* __restrict__ a_node,
                                                const float* __restrict__ a_gn)
{
    __shared__ float sW[FF * 65];    // stride-65 pad: conflict-free both axes
    __shared__ float sWi[FF * 65];
    __shared__ float sx[32 * 65];
    __shared__ float sa_n[FF], sa_g[FF];
    __shared__ float sp_n[FF], sp_g[FF];

    int tid = threadIdx.x;

    if (blockIdx.x >= 512) {
        // ---- member-list compaction: warp handles one edge ----
        int e = (int)(blockIdx.x - 512) * 8 + (tid >> 5);
        int lane = tid & 31;
        int cnt = 0;
        for (int base = 0; base < NN; base += 32) {
            int n = base + lane;
            bool m = H[n * EE + e] > 0.f;
            unsigned bm = __ballot_sync(0xffffffffu, m);
            if (m) g_emem[e * NN + cnt + __popc(bm & ((1u << lane) - 1u))] = n;
            cnt += __popc(bm);
        }
        if (lane == 0) g_ecnt[e] = cnt;
        return;
    }

    for (int i = tid; i < FF * FF; i += 256) {
        int k = i >> 6, f = i & 63;
        sW[k * 65 + f]  = W[i];
        sWi[k * 65 + f] = Wi[i];
    }
    if (tid < FF) { sa_n[tid] = a_node[tid]; sa_g[tid] = a_gn[tid]; }

    long pbase = (long)blockIdx.x * 32;
    for (int i = tid; i < 32 * FF; i += 256)
        sx[(i >> 6) * 65 + (i & 63)] = x[(pbase + (i >> 6)) * FF + (i & 63)];
    __syncthreads();

    // p_node[k] = W[k,:].a_node ; p_gn[k] = W[k,:].a_gn
    if (tid < 64) {
        int k = tid; float p = 0.f;
        #pragma unroll
        for (int f = 0; f < FF; ++f) p += sW[k * 65 + f] * sa_n[f];
        sp_n[k] = p;
    } else if (tid < 128) {
        int k = tid - 64; float p = 0.f;
        #pragma unroll
        for (int f = 0; f < FF; ++f) p += sW[k * 65 + f] * sa_g[f];
        sp_g[k] = p;
    }
    __syncthreads();

    int f = tid & 63, grp = tid >> 6;
    #pragma unroll
    for (int it = 0; it < 8; ++it) {
        int nl = grp * 8 + it;
        long pair = pbase + nl;
        const float* xr = &sx[nl * 65];
        float hv = 0.f, xv = 0.f;
        #pragma unroll
        for (int k = 0; k < FF; ++k) {
            float xk = xr[k];
            hv += xk * sW[k * 65 + f];
            xv += xk * sWi[k * 65 + f];
        }
        g_h[pair * FF + f]  = hv;
        g_xw[pair * FF + f] = xv;
    }

    // s = lrelu(x.p_node), hn = x.p_gn (32+32 threads, serial 64-FMA dots)
    if (tid < 32) {
        int r = tid; long pair = pbase + r;
        float s = 0.f;
        #pragma unroll
        for (int k = 0; k < FF; ++k) s += sx[r * 65 + k] * sp_n[k];
        g_s[pair] = (s >= 0.f) ? s : 0.2f * s;
    } else if (tid < 64) {
        int r = tid - 32; long pair = pbase + r;
        float hn = 0.f;
        #pragma unroll
        for (int k = 0; k < FF; ++k) hn += sx[r * 65 + k] * sp_g[k];
        g_hn[pair] = hn;
    }
}

// =======================================================================
// K2 (fused): blocks 0..2047  -> industry gather (one node each)
//             blocks 2048..2559 -> per-(b,e) edge softmax/agg/scores
// Both paths use 512 threads; smem shared via union.
// =======================================================================
struct SmInd  { int seg[2048]; int clist[2048]; int wcnt[16]; int woff[16]; int stot; };
struct SmEdge { float red[16]; float swv[512]; float sagg[FF]; float selu[FF]; float comb[512]; };
union SmU { SmInd ind; SmEdge edge; };

__global__ __launch_bounds__(512) void k_ind_edge(const float* __restrict__ adj,
                                                  const float* __restrict__ a_ge,
                                                  const float* __restrict__ fcW,
                                                  const float* __restrict__ fcb,
                                                  const float* __restrict__ av)
{
    __shared__ SmU sm;
    int tid = threadIdx.x;
    int wid = tid >> 5, lane = tid & 31;

    if (blockIdx.x < 2048) {
        // ================= industry path =================
        int n = blockIdx.x;
        int b = tid >> 6, f = tid & 63;
        const float* row = adj + (long)n * NN;

        int base = wid * 128;
        int cnt = 0;
        #pragma unroll
        for (int j = 0; j < 4; ++j) {
            int m = base + j * 32 + lane;
            bool p = row[m] > 0.f;
            unsigned bm = __ballot_sync(0xffffffffu, p);
            if (p) sm.ind.seg[base + cnt + __popc(bm & ((1u << lane) - 1u))] = m;
            cnt += __popc(bm);
        }
        if (lane == 0) sm.ind.wcnt[wid] = cnt;
        __syncthreads();

        if (tid < 32) {
            int c = (lane < 16) ? sm.ind.wcnt[lane] : 0;
            int s = c;
            #pragma unroll
            for (int o = 1; o < 16; o <<= 1) {
                int t = __shfl_up_sync(0xffffffffu, s, o);
                if (lane >= o) s += t;
            }
            if (lane < 16) sm.ind.woff[lane] = s - c;
            if (lane == 15) sm.ind.stot = s;
        }
        __syncthreads();

        {
            int c = sm.ind.wcnt[wid], o = sm.ind.woff[wid];
            for (int j = lane; j < c; j += 32) sm.ind.clist[o + j] = sm.ind.seg[wid * 128 + j];
        }
        __syncthreads();

        int total = sm.ind.stot;
        const float* xwb = g_xw + (long)b * NN * FF + f;

        float acc = 0.f;
        for (int i = 0; i < total; i += 8) {
            int   id[8];
            float v[8];
            #pragma unroll
            for (int j = 0; j < 8; ++j) id[j] = (i + j < total) ? sm.ind.clist[i + j] : sm.ind.clist[0];
            #pragma unroll
            for (int j = 0; j < 8; ++j) v[j] = xwb[(long)id[j] * FF];
            #pragma unroll
            for (int j = 0; j < 8; ++j) if (i + j < total) acc += v[j];
        }
        float d = (total < 1) ? 1.f : (float)total;
        g_ind[((long)b * NN + n) * FF + f] = acc / d;
        return;
    }

    // ================= edge path =================
    int idx = (int)blockIdx.x - 2048;
    int e = idx & 63, b = idx >> 6;
    int M = g_ecnt[e];

    if (M == 0) {
        if (tid < FF) g_agg[((b * EE) + e) * FF + tid] = 0.f;
        if (tid == 0) { g_ge[b * EE + e] = 0.f; g_se[b * EE + e] = 0.f; }
        return;
    }

    const int*   mem = &g_emem[e * NN];
    const float* sb  = &g_s[b * NN];

    // ---- max over member scores ----
    float mx = -1e30f;
    for (int i = tid; i < M; i += 512) mx = fmaxf(mx, sb[mem[i]]);
    #pragma unroll
    for (int o = 16; o; o >>= 1) mx = fmaxf(mx, __shfl_xor_sync(0xffffffffu, mx, o));
    if (lane == 0) sm.edge.red[wid] = mx;
    __syncthreads();
    float maxv = sm.edge.red[0];
    #pragma unroll
    for (int w2 = 1; w2 < 16; ++w2) maxv = fmaxf(maxv, sm.edge.red[w2]);
    __syncthreads();

    // ---- sum of exp; stash weights ----
    float ps = 0.f;
    for (int i = tid; i < M; i += 512) {
        float w = __expf(sb[mem[i]] - maxv);
        if (i < 512) sm.edge.swv[i] = w;
        ps += w;
    }
    #pragma unroll
    for (int o = 16; o; o >>= 1) ps += __shfl_xor_sync(0xffffffffu, ps, o);
    if (lane == 0) sm.edge.red[wid] = ps;
    __syncthreads();
    float ssum = 0.f;
    #pragma unroll
    for (int w2 = 0; w2 < 16; ++w2) ssum += sm.edge.red[w2];
    float inv = 1.f / ssum;

    // ---- agg[f] = sum_i alpha_i h[b, m_i, f] (8-way member split) ----
    int f = tid & 63, q = tid >> 6;
    float acc = 0.f;
    for (int i = q; i < M; i += 8) {
        float w = (i < 512) ? sm.edge.swv[i] : __expf(sb[mem[i]] - maxv);
        acc += w * g_h[((long)b * NN + mem[i]) * FF + f];
    }
    sm.edge.comb[tid] = acc;
    __syncthreads();
    if (tid < FF) {
        float a = 0.f;
        #pragma unroll
        for (int j = 0; j < 8; ++j) a += sm.edge.comb[tid + 64 * j];
        a *= inv;
        sm.edge.sagg[tid] = a;
        g_agg[((b * EE) + e) * FF + tid] = a;
        sm.edge.selu[tid] = (a > 0.f) ? a : expm1f(a);
    }
    __syncthreads();

    // ---- ge = agg . a_ge (threads 0..63) ----
    float pg = (tid < FF) ? sm.edge.sagg[tid] * a_ge[tid] : 0.f;
    #pragma unroll
    for (int o = 16; o; o >>= 1) pg += __shfl_xor_sync(0xffffffffu, pg, o);
    __syncthreads();
    if (tid < 64 && lane == 0) sm.edge.red[wid] = pg;
    __syncthreads();
    if (tid == 0) g_ge[b * EE + e] = sm.edge.red[0] + sm.edge.red[1];

    // ---- se = tanh(elu(agg) @ fcW + fcb) . av  (threads 0..127) ----
    float pv = 0.f;
    if (tid < FC) {
        float z = fcb[tid];
        #pragma unroll
        for (int f2 = 0; f2 < FF; ++f2) z += sm.edge.selu[f2] * __ldg(&fcW[f2 * FC + tid]);
        pv = av[tid] * ftanh(z);
    }
    #pragma unroll
    for (int o = 16; o; o >>= 1) pv += __shfl_xor_sync(0xffffffffu, pv, o);
    __syncthreads();
    if (tid < 128 && lane == 0) sm.edge.red[wid] = pv;
    __syncthreads();
    if (tid == 0) g_se[b * EE + e] = sm.edge.red[0] + sm.edge.red[1] + sm.edge.red[2] + sm.edge.red[3];
}

// =======================================================================
// K3: one WARP per (b,n) pair. 512 threads = 16 pairs/block.
// Fast tanh, ballot-sparse e-loop, float2-interleaved matvec operand.
// =======================================================================
__global__ __launch_bounds__(512) void k_final(const float* __restrict__ Hm,
                                               const float* __restrict__ fcW,
                                               const float* __restrict__ fcb,
                                               const float* __restrict__ av,
                                               float* __restrict__ out)
{
    __shared__ float sfc[FF * FC];     // 32 KB
    __shared__ float sfcb[FC], sav[FC];
    __shared__ float2 swig[16][FF];    // per-warp (industry, g) interleaved

    int tid = threadIdx.x, w = tid >> 5, lane = tid & 31;
    for (int i = tid; i < FF * FC; i += 512) sfc[i] = fcW[i];
    if (tid < FC) { sfcb[tid] = fcb[tid]; sav[tid] = av[tid]; }
    __syncthreads();

    long pair = (long)blockIdx.x * 16 + w;
    int b = (int)(pair >> 11), n = (int)(pair & 2047);
    int f0 = lane, f1 = lane + 32;

    float ind0 = g_ind[pair * FF + f0], ind1 = g_ind[pair * FF + f1];
    float h0   = g_h[pair * FF + f0],   h1   = g_h[pair * FF + f1];
    float hnv  = g_hn[pair];

    // ---- coefs1: masked softmax over this node's member edges (lane owns e0,e1)
    bool m0 = Hm[(long)n * EE + lane] > 0.f;
    bool m1 = Hm[(long)n * EE + lane + 32] > 0.f;
    unsigned mask0 = __ballot_sync(0xffffffffu, m0);
    unsigned mask1 = __ballot_sync(0xffffffffu, m1);
    float se0 = m0 ? g_se[b * EE + lane]      : -1e30f;
    float se1 = m1 ? g_se[b * EE + lane + 32] : -1e30f;
    float mx = fmaxf(se0, se1);
    #pragma unroll
    for (int o = 16; o; o >>= 1) mx = fmaxf(mx, __shfl_xor_sync(0xffffffffu, mx, o));
    float ex0 = m0 ? __expf(se0 - mx) : 0.f;
    float ex1 = m1 ? __expf(se1 - mx) : 0.f;
    float sum = ex0 + ex1;
    #pragma unroll
    for (int o = 16; o; o >>= 1) sum += __shfl_xor_sync(0xffffffffu, sum, o);
    float inv = 1.f / sum;
    float c0 = ex0 * inv, c1 = ex1 * inv;
    float bt0 = m0 ? __fdividef(1.f, 1.f + __expf(-(hnv + g_ge[b * EE + lane])))      : 0.f;
    float bt1 = m1 ? __fdividef(1.f, 1.f + __expf(-(hnv + g_ge[b * EE + lane + 32]))) : 0.f;

    // ---- g[f] = sum over member edges only (ballot-driven, ~2.9 iters) ----
    float gv0 = 0.f, gv1 = 0.f;
    const float* aggb = g_agg + ((long)b * EE) * FF;
    while (mask0) {
        int e = __ffs(mask0) - 1; mask0 &= mask0 - 1;
        float ce = __shfl_sync(0xffffffffu, c0, e);
        float bt = __shfl_sync(0xffffffffu, bt0, e);
        float a0 = aggb[e * FF + f0], a1 = aggb[e * FF + f1];
        float v0 = fmaf(bt, h0 - a0, a0);
        float v1 = fmaf(bt, h1 - a1, a1);
        gv0 += ce * ((v0 > 0.f) ? v0 : expm1f(v0));
        gv1 += ce * ((v1 > 0.f) ? v1 : expm1f(v1));
    }
    while (mask1) {
        int e = __ffs(mask1) - 1; mask1 &= mask1 - 1;
        float ce = __shfl_sync(0xffffffffu, c1, e);
        float bt = __shfl_sync(0xffffffffu, bt1, e);
        int eg = e + 32;
        float a0 = aggb[eg * FF + f0], a1 = aggb[eg * FF + f1];
        float v0 = fmaf(bt, h0 - a0, a0);
        float v1 = fmaf(bt, h1 - a1, a1);
        gv0 += ce * ((v0 > 0.f) ? v0 : expm1f(v0));
        gv1 += ce * ((v1 > 0.f) ? v1 : expm1f(v1));
    }

    swig[w][f0] = make_float2(ind0, gv0);
    swig[w][f1] = make_float2(ind1, gv1);
    __syncwarp();

    // ---- pair attention: two 128-col tanh matvecs, lane owns 4 contiguous cols
    float z1[4], z2[4];
    #pragma unroll
    for (int j = 0; j < 4; ++j) { z1[j] = sfcb[lane * 4 + j]; z2[j] = z1[j]; }
    #pragma unroll 4
    for (int f2 = 0; f2 < FF; ++f2) {
        float2 ig = swig[w][f2];                               // LDS.64 broadcast
        float4 wv = *(const float4*)&sfc[f2 * FC + lane * 4];  // LDS.128
        z1[0] += ig.x * wv.x; z1[1] += ig.x * wv.y; z1[2] += ig.x * wv.z; z1[3] += ig.x * wv.w;
        z2[0] += ig.y * wv.x; z2[1] += ig.y * wv.y; z2[2] += ig.y * wv.z; z2[3] += ig.y * wv.w;
    }
    float p1 = 0.f, p2 = 0.f;
    #pragma unroll
    for (int j = 0; j < 4; ++j) {
        float a = sav[lane * 4 + j];
        p1 += a * ftanh(z1[j]);
        p2 += a * ftanh(z2[j]);
    }
    #pragma unroll
    for (int o = 16; o; o >>= 1) {
        p1 += __shfl_xor_sync(0xffffffffu, p1, o);
        p2 += __shfl_xor_sync(0xffffffffu, p2, o);
    }

    float mm = fmaxf(p1, p2);
    float q1 = __expf(p1 - mm), q2 = __expf(p2 - mm);
    float cc = q1 / (q1 + q2);
    out[pair * FF + f0] = fmaf(cc, ind0 - gv0, gv0);
    out[pair * FF + f1] = fmaf(cc, ind1 - gv1, gv1);
}

// =======================================================================
// launcher
// =======================================================================
extern "C" void kernel_launch(void* const* d_in, const int* in_sizes, int n_in,
                              void* d_out, int out_size)
{
    const float* x   = (const float*)d_in[0];
    const float* H   = (const float*)d_in[1];
    const float* adj = (const float*)d_in[2];
    int wb = (n_in >= 12 && in_sizes[3] == 1) ? 4 : 3;
    const float* W      = (const float*)d_in[wb + 0];
    const float* W_ind  = (const float*)d_in[wb + 1];
    const float* a_node = (const float*)d_in[wb + 2];
    const float* a_gn   = (const float*)d_in[wb + 3];
    const float* a_ge   = (const float*)d_in[wb + 4];
    const float* fcW    = (const float*)d_in[wb + 5];
    const float* fcb    = (const float*)d_in[wb + 6];
    const float* av     = (const float*)d_in[wb + 7];
    float* out = (float*)d_out;

    k_h_emem<<<520, 256>>>(x, H, W, W_ind, a_node, a_gn);
    k_ind_edge<<<2048 + EE * BB, 512>>>(adj, a_ge, fcW, fcb, av);
    k_final<<<(BB * NN) / 16, 512>>>(H, fcW, fcb, av, out);
}